// round 15
// baseline (speedup 1.0000x reference)
#include <cuda_runtime.h>
#include <cuda_bf16.h>
#include <cstdint>

#define N_NODES 100000
#define N_EDGES 1600000
#define D 128
#define N_CONVS 6

// ---------------- scratch (static device memory; no allocs allowed) ----------
__device__ __align__(16) float g_bufA[N_NODES * D];
__device__ __align__(16) float g_bufB[N_NODES * D];
__device__ __align__(16) float g_mean[N_NODES * D];
// pre-split bf16 W, fragment-major: [layer][mat][kc(4)][hi:1024 | lo:1024] uint2
__device__ __align__(16) uint2 g_Wbf[N_CONVS * 2 * 4 * 2048];
__device__ float g_deg_inv[N_NODES];
__device__ int   g_deg[N_NODES];
__device__ int   g_row_ptr[N_NODES + 1];
__device__ int   g_cursor[N_NODES];
__device__ int   g_col_idx[N_EDGES];
__device__ int   g_blocksum[128];
__device__ int   g_is64;

// ---------------- helpers -----------------------------------------------------
__device__ __forceinline__ uint32_t packbf(float a, float b) {
    __nv_bfloat162 t = __floats2bfloat162_rn(a, b);   // .x = a (low half)
    return *(uint32_t*)&t;
}
__device__ __forceinline__ float bfhi(float w) {
    return __bfloat162float(__float2bfloat16_rn(w));
}

// ---------------- edge dtype detection ---------------------------------------
__global__ void detect_kernel(const void* __restrict__ ei) {
    const long long* p64 = (const long long*)ei;
    int ok = 1;
    for (int i = 0; i < 64; i++) {
        long long v = p64[i];
        if (v < 0 || v >= N_NODES) { ok = 0; break; }
    }
    g_is64 = ok;
}

__device__ __forceinline__ int load_edge(const void* ei, long idx) {
    long long v = g_is64 ? ((const long long*)ei)[idx]
                         : (long long)((const int*)ei)[idx];
    if ((unsigned long long)v >= (unsigned long long)N_NODES) v = 0;
    return (int)v;
}

// ---------------- CSR build --------------------------------------------------
__global__ void zero_deg_kernel() {
    int i = blockIdx.x * blockDim.x + threadIdx.x;
    if (i < N_NODES) g_deg[i] = 0;
}

__global__ void count_deg_kernel(const void* __restrict__ ei) {
    int e = blockIdx.x * blockDim.x + threadIdx.x;
    if (e < N_EDGES) atomicAdd(&g_deg[load_edge(ei, (long)N_EDGES + e)], 1);
}

#define SCAN_T 1024
#define SCAN_BLOCKS ((N_NODES + SCAN_T - 1) / SCAN_T)

__global__ __launch_bounds__(SCAN_T) void scanA_kernel() {
    __shared__ int sh[SCAN_T];
    int i = blockIdx.x * SCAN_T + threadIdx.x;
    int v = (i < N_NODES) ? g_deg[i] : 0;
    sh[threadIdx.x] = v;
    __syncthreads();
    int acc = v;
    for (int off = 1; off < SCAN_T; off <<= 1) {
        int t = (threadIdx.x >= off) ? sh[threadIdx.x - off] : 0;
        __syncthreads();
        acc += t;
        sh[threadIdx.x] = acc;
        __syncthreads();
    }
    if (i < N_NODES) g_row_ptr[i] = acc - v;
    if (threadIdx.x == SCAN_T - 1) g_blocksum[blockIdx.x] = acc;
}

__global__ void scanB_kernel() {
    __shared__ int sh[128];
    int t = threadIdx.x;
    int v = (t < SCAN_BLOCKS) ? g_blocksum[t] : 0;
    sh[t] = v;
    __syncthreads();
    int acc = v;
    for (int off = 1; off < 128; off <<= 1) {
        int tv = (t >= off) ? sh[t - off] : 0;
        __syncthreads();
        acc += tv;
        sh[t] = acc;
        __syncthreads();
    }
    if (t < SCAN_BLOCKS) g_blocksum[t] = acc - v;
}

__global__ __launch_bounds__(SCAN_T) void scanC_kernel() {
    int i = blockIdx.x * SCAN_T + threadIdx.x;
    if (i < N_NODES) {
        int r = g_row_ptr[i] + g_blocksum[blockIdx.x];
        g_row_ptr[i] = r;
        g_cursor[i] = r;
        g_deg_inv[i] = 1.0f / (float)max(g_deg[i], 1);
    }
    if (i == 0) g_row_ptr[N_NODES] = N_EDGES;
}

__global__ void fill_csr_kernel(const void* __restrict__ ei) {
    int e = blockIdx.x * blockDim.x + threadIdx.x;
    if (e < N_EDGES) {
        int src = load_edge(ei, e);
        int dst = load_edge(ei, (long)N_EDGES + e);
        int p = atomicAdd(&g_cursor[dst], 1);
        if (p < N_EDGES) g_col_idx[p] = src;
    }
}

// ---------------- W pre-split to bf16 fragment-major (once per launch) --------
__global__ void wsplit_kernel(const float* __restrict__ Wl,
                              const float* __restrict__ Wr) {
    int t = blockIdx.x * 256 + threadIdx.x;           // 6*2*4*1024
    if (t >= N_CONVS * 2 * 4 * 1024) return;
    int f     = t & 1023;
    int kc    = (t >> 10) & 3;
    int mat   = (t >> 12) & 1;
    int layer = t >> 13;
    int s  = f >> 9;
    int n  = (f >> 2) & 127;
    int qq = f & 3;
    const float* W = (mat ? Wr : Wl) + (long)layer * D * D;
    int kb = kc * 32 + s * 16 + 2 * qq;
    float w0 = W[(kb + 0) * D + n];
    float w1 = W[(kb + 1) * D + n];
    float w2 = W[(kb + 8) * D + n];
    float w3 = W[(kb + 9) * D + n];
    float h0 = bfhi(w0), h1 = bfhi(w1), h2 = bfhi(w2), h3 = bfhi(w3);
    uint2 hi, lo;
    hi.x = packbf(h0, h1);        hi.y = packbf(h2, h3);
    lo.x = packbf(w0 - h0, w1 - h1);
    lo.y = packbf(w2 - h2, w3 - h3);
    uint2* dst = g_Wbf + (long)(((layer * 2 + mat) * 4 + kc)) * 2048;
    dst[f] = hi;
    dst[1024 + f] = lo;
}

// ---------------- mean aggregation: one warp per node, 4-deep ILP ------------
__global__ __launch_bounds__(256) void agg_kernel(const float* __restrict__ x) {
    int warp = (blockIdx.x * blockDim.x + threadIdx.x) >> 5;
    int lane = threadIdx.x & 31;
    if (warp >= N_NODES) return;

    int e0 = g_row_ptr[warp];
    int e1 = g_row_ptr[warp + 1];
    const float4* x4 = (const float4*)x;

    float4 a0 = make_float4(0.f, 0.f, 0.f, 0.f);
    float4 a1 = a0, a2 = a0, a3 = a0;
    int e = e0;
    for (; e + 4 <= e1; e += 4) {
        int s0 = g_col_idx[e + 0];
        int s1 = g_col_idx[e + 1];
        int s2 = g_col_idx[e + 2];
        int s3 = g_col_idx[e + 3];
        float4 v0 = __ldg(&x4[(long)s0 * 32 + lane]);
        float4 v1 = __ldg(&x4[(long)s1 * 32 + lane]);
        float4 v2 = __ldg(&x4[(long)s2 * 32 + lane]);
        float4 v3 = __ldg(&x4[(long)s3 * 32 + lane]);
        a0.x += v0.x; a0.y += v0.y; a0.z += v0.z; a0.w += v0.w;
        a1.x += v1.x; a1.y += v1.y; a1.z += v1.z; a1.w += v1.w;
        a2.x += v2.x; a2.y += v2.y; a2.z += v2.z; a2.w += v2.w;
        a3.x += v3.x; a3.y += v3.y; a3.z += v3.z; a3.w += v3.w;
    }
    for (; e < e1; e++) {
        int s = g_col_idx[e];
        float4 v = __ldg(&x4[(long)s * 32 + lane]);
        a0.x += v.x; a0.y += v.y; a0.z += v.z; a0.w += v.w;
    }
    float di = g_deg_inv[warp];
    float4 acc;
    acc.x = (a0.x + a1.x + a2.x + a3.x) * di;
    acc.y = (a0.y + a1.y + a2.y + a3.y) * di;
    acc.z = (a0.z + a1.z + a2.z + a3.z) * di;
    acc.w = (a0.w + a1.w + a2.w + a3.w) * di;
    ((float4*)g_mean)[(long)warp * 32 + lane] = acc;
}

// ---------------- 3xBF16 half-GEMM (one matrix), double-buffered --------------
// mode 0: Y = A@W + bias        (xwr half; runs concurrently with agg)
// mode 1: Y = relu(A@W + Y)     (mwl half; consumes mean and partial Y)
#define APITCH 20
#define AS_BUF_STRIDE (2 * 128 * APITCH)      // 5120 u32 per buffer
#define WS_BASE_U32   (2 * AS_BUF_STRIDE)     // 10240
#define WS_BUF_STRIDE 2048                    // uint2 per buffer (hi 1024 | lo 1024)
#define SMEM_BYTES ((WS_BASE_U32 + 2 * WS_BUF_STRIDE * 2) * 4)   // 73728 B

__device__ __forceinline__ void mma_bf16(float c[4],
                                         uint32_t a0, uint32_t a1,
                                         uint32_t a2, uint32_t a3,
                                         uint32_t b0, uint32_t b1) {
    asm volatile(
        "mma.sync.aligned.m16n8k16.row.col.f32.bf16.bf16.f32 "
        "{%0,%1,%2,%3}, {%4,%5,%6,%7}, {%8,%9}, {%0,%1,%2,%3};"
        : "+f"(c[0]), "+f"(c[1]), "+f"(c[2]), "+f"(c[3])
        : "r"(a0), "r"(a1), "r"(a2), "r"(a3), "r"(b0), "r"(b1));
}

__global__ __launch_bounds__(256, 2) void sage_gemm_half(
    const float* __restrict__ A,     // [N,128] (x or mean)
    const uint2* __restrict__ Wbf4,  // 4 ktiles x 2048 uint2 for ONE matrix
    const float* __restrict__ bias,  // [128] (mode 0) / unused (mode 1)
    float* __restrict__ Y,
    int mode)
{
    extern __shared__ __align__(16) uint32_t dsm[];
    uint32_t* AsB = dsm;
    uint2*    WsB = (uint2*)(dsm + WS_BASE_U32);

    const int tid  = threadIdx.x;
    const int wid  = tid >> 5;
    const int lane = tid & 31;
    const int rr   = lane >> 2;
    const int qq   = lane & 3;
    const int wm   = (wid & 3) * 32;
    const int wn   = (wid >> 2) * 64;
    const int row0 = blockIdx.x * 128;

    float c[2][8][4];
#pragma unroll
    for (int mt = 0; mt < 2; mt++)
#pragma unroll
        for (int nt = 0; nt < 8; nt++)
#pragma unroll
            for (int i = 0; i < 4; i++) c[mt][nt][i] = 0.f;

    const float4* A4 = (const float4*)A;

    float4 va[4];
    uint4  vw[4];

    // --- prologue: prefetch ktile 0 ---
    {
#pragma unroll
        for (int i = 0; i < 4; i++) {
            int idx = tid + i * 256;
            int r  = idx >> 3;
            int c4 = idx & 7;
            int rg = row0 + r;
            if (rg >= N_NODES) rg = N_NODES - 1;
            va[i] = A4[(long)rg * 32 + c4];
        }
        const uint4* src = (const uint4*)Wbf4;
#pragma unroll
        for (int i = 0; i < 4; i++) vw[i] = src[tid + i * 256];
    }

    for (int it = 0; it < 4; ++it) {
        const int bi = it & 1;
        uint32_t* As = AsB + bi * AS_BUF_STRIDE;
        uint2*    Ws = WsB + bi * WS_BUF_STRIDE;

#pragma unroll
        for (int i = 0; i < 4; i++) {
            int idx = tid + i * 256;
            int r  = idx >> 3;
            int c4 = idx & 7;
            float4 v = va[i];
            float hx = bfhi(v.x), hy = bfhi(v.y), hz = bfhi(v.z), hw = bfhi(v.w);
            As[r * APITCH + c4 * 2 + 0] = packbf(hx, hy);
            As[r * APITCH + c4 * 2 + 1] = packbf(hz, hw);
            As[128 * APITCH + r * APITCH + c4 * 2 + 0] = packbf(v.x - hx, v.y - hy);
            As[128 * APITCH + r * APITCH + c4 * 2 + 1] = packbf(v.z - hz, v.w - hw);
        }
        {
            uint4* dst = (uint4*)Ws;
#pragma unroll
            for (int i = 0; i < 4; i++) dst[tid + i * 256] = vw[i];
        }
        __syncthreads();

        if (it < 3) {
            int nit = it + 1;
#pragma unroll
            for (int i = 0; i < 4; i++) {
                int idx = tid + i * 256;
                int r  = idx >> 3;
                int c4 = idx & 7;
                int rg = row0 + r;
                if (rg >= N_NODES) rg = N_NODES - 1;
                va[i] = A4[(long)rg * 32 + nit * 8 + c4];
            }
            const uint4* src = (const uint4*)(Wbf4 + (long)nit * 2048);
#pragma unroll
            for (int i = 0; i < 4; i++) vw[i] = src[tid + i * 256];
        }

#pragma unroll
        for (int s = 0; s < 2; s++) {
            uint32_t ah[2][4], al[2][4];
#pragma unroll
            for (int mt = 0; mt < 2; mt++) {
                int r = wm + mt * 16 + rr;
                int p = s * 8 + qq;
                ah[mt][0] = As[r * APITCH + p];
                ah[mt][1] = As[(r + 8) * APITCH + p];
                ah[mt][2] = As[r * APITCH + p + 4];
                ah[mt][3] = As[(r + 8) * APITCH + p + 4];
                al[mt][0] = As[128 * APITCH + r * APITCH + p];
                al[mt][1] = As[128 * APITCH + (r + 8) * APITCH + p];
                al[mt][2] = As[128 * APITCH + r * APITCH + p + 4];
                al[mt][3] = As[128 * APITCH + (r + 8) * APITCH + p + 4];
            }
#pragma unroll
            for (int nt = 0; nt < 8; nt++) {
                int widx = (s * 128 + wn + nt * 8 + rr) * 4 + qq;
                uint2 bh = Ws[widx];
                uint2 bl = Ws[1024 + widx];
#pragma unroll
                for (int mt = 0; mt < 2; mt++) {
                    mma_bf16(c[mt][nt], ah[mt][0], ah[mt][1], ah[mt][2], ah[mt][3], bh.x, bh.y);
                    mma_bf16(c[mt][nt], ah[mt][0], ah[mt][1], ah[mt][2], ah[mt][3], bl.x, bl.y);
                    mma_bf16(c[mt][nt], al[mt][0], al[mt][1], al[mt][2], al[mt][3], bh.x, bh.y);
                }
            }
        }
    }

    // epilogue
#pragma unroll
    for (int mt = 0; mt < 2; mt++) {
#pragma unroll
        for (int half = 0; half < 2; half++) {
            int r = row0 + wm + mt * 16 + rr + half * 8;
            if (r < N_NODES) {
#pragma unroll
                for (int nt = 0; nt < 8; nt++) {
                    int col = wn + nt * 8 + 2 * qq;
                    float v0 = c[mt][nt][half * 2 + 0];
                    float v1 = c[mt][nt][half * 2 + 1];
                    float2 o;
                    if (mode == 0) {
                        o.x = v0 + bias[col];
                        o.y = v1 + bias[col + 1];
                    } else {
                        float2 p = *(const float2*)&Y[(long)r * 128 + col];
                        o.x = fmaxf(v0 + p.x, 0.f);
                        o.y = fmaxf(v1 + p.y, 0.f);
                    }
                    *(float2*)&Y[(long)r * 128 + col] = o;
                }
            }
        }
    }
}

// ---------------- final linear ------------------------------------------------
__global__ __launch_bounds__(256) void final_kernel(
    const float* __restrict__ x, const float* __restrict__ W_lin,
    const float* __restrict__ b_lin, float* __restrict__ out)
{
    int warp = (blockIdx.x * blockDim.x + threadIdx.x) >> 5;
    int lane = threadIdx.x & 31;
    if (warp >= N_NODES) return;

    const float4* x4 = (const float4*)x;
    float4 xv = x4[(long)warp * 32 + lane];
    float w0 = W_lin[lane * 4 + 0];
    float w1 = W_lin[lane * 4 + 1];
    float w2 = W_lin[lane * 4 + 2];
    float w3 = W_lin[lane * 4 + 3];
    float s = xv.x * w0 + xv.y * w1 + xv.z * w2 + xv.w * w3;
#pragma unroll
    for (int off = 16; off > 0; off >>= 1)
        s += __shfl_xor_sync(0xFFFFFFFFu, s, off);
    if (lane == 0) out[warp] = s + b_lin[0];
}

// ---------------- launch ------------------------------------------------------
extern "C" void kernel_launch(void* const* d_in, const int* in_sizes, int n_in,
                              void* d_out, int out_size)
{
    const float* x     = (const float*)d_in[0];
    const void*  ei    = d_in[1];
    const float* Wl    = (const float*)d_in[2];
    const float* Wr    = (const float*)d_in[3];
    const float* b     = (const float*)d_in[4];
    const float* W_lin = (const float*)d_in[5];
    const float* b_lin = (const float*)d_in[6];
    float*       out   = (float*)d_out;

    float *bufA, *bufB, *meanp;
    uint2* wbf;
    cudaGetSymbolAddress((void**)&bufA, g_bufA);
    cudaGetSymbolAddress((void**)&bufB, g_bufB);
    cudaGetSymbolAddress((void**)&meanp, g_mean);
    cudaGetSymbolAddress((void**)&wbf, g_Wbf);

    cudaFuncSetAttribute(sage_gemm_half,
                         cudaFuncAttributeMaxDynamicSharedMemorySize, SMEM_BYTES);

    // side stream + events for agg||xwr overlap (created per call; kernel_launch
    // runs only a handful of times — correctness + capture — so no cleanup needed,
    // and no static guards).
    cudaStream_t s2;
    cudaStreamCreateWithFlags(&s2, cudaStreamNonBlocking);
    cudaEvent_t evFork[N_CONVS], evJoin[N_CONVS];
    for (int i = 0; i < N_CONVS; i++) {
        cudaEventCreateWithFlags(&evFork[i], cudaEventDisableTiming);
        cudaEventCreateWithFlags(&evJoin[i], cudaEventDisableTiming);
    }

    detect_kernel<<<1, 1>>>(ei);
    zero_deg_kernel<<<(N_NODES + 255) / 256, 256>>>();
    count_deg_kernel<<<(N_EDGES + 255) / 256, 256>>>(ei);
    scanA_kernel<<<SCAN_BLOCKS, SCAN_T>>>();
    scanB_kernel<<<1, 128>>>();
    scanC_kernel<<<SCAN_BLOCKS, SCAN_T>>>();
    fill_csr_kernel<<<(N_EDGES + 255) / 256, 256>>>(ei);
    wsplit_kernel<<<(N_CONVS * 2 * 4 * 1024 + 255) / 256, 256>>>(Wl, Wr);

    const int aggBlocks  = (N_NODES * 32 + 255) / 256;
    const int gemmBlocks = (N_NODES + 127) / 128;

    const float* cur = x;
    for (int i = 0; i < N_CONVS; i++) {
        float* nxt = (i & 1) ? bufB : bufA;
        const uint2* wl4 = wbf + (long)(i * 2 + 0) * 4 * 2048;
        const uint2* wr4 = wbf + (long)(i * 2 + 1) * 4 * 2048;

        // fork: xwr half on s2 (independent of agg)
        cudaEventRecord(evFork[i], 0);
        cudaStreamWaitEvent(s2, evFork[i], 0);
        sage_gemm_half<<<gemmBlocks, 256, SMEM_BYTES, s2>>>(
            cur, wr4, b + (long)i * D, nxt, 0);
        cudaEventRecord(evJoin[i], s2);

        // agg on main stream, concurrent with xwr
        agg_kernel<<<aggBlocks, 256>>>(cur);

        // join, then mwl half consumes mean + partial Y
        cudaStreamWaitEvent(0, evJoin[i], 0);
        sage_gemm_half<<<gemmBlocks, 256, SMEM_BYTES>>>(
            meanp, wl4, nullptr, nxt, 1);
        cur = nxt;
    }
    final_kernel<<<aggBlocks, 256>>>(cur, W_lin, b_lin, out);
}

// round 16
// speedup vs baseline: 1.2131x; 1.2131x over previous
#include <cuda_runtime.h>
#include <cuda_bf16.h>
#include <cstdint>

#define N_NODES 100000
#define N_EDGES 1600000
#define D 128
#define N_CONVS 6

// chunking for agg||gemm pipeline (chunk boundary multiple of 128)
#define C0_NODES 50048
#define C1_NODES (N_NODES - C0_NODES)          // 49952
#define C0_GBLOCKS (C0_NODES / 128)            // 391
#define C1_GBLOCKS ((C1_NODES + 127) / 128)    // 391

// ---------------- scratch (static device memory; no allocs allowed) ----------
__device__ __align__(16) float g_bufA[N_NODES * D];
__device__ __align__(16) float g_bufB[N_NODES * D];
__device__ __align__(16) float g_mean[N_NODES * D];
// pre-split bf16 W, fragment-major: [layer][mat][kc(4)][hi:1024 | lo:1024] uint2
__device__ __align__(16) uint2 g_Wbf[N_CONVS * 2 * 4 * 2048];
__device__ float g_deg_inv[N_NODES];
__device__ int   g_deg[N_NODES];
__device__ int   g_row_ptr[N_NODES + 1];
__device__ int   g_cursor[N_NODES];
__device__ int   g_col_idx[N_EDGES];
__device__ int   g_blocksum[128];
__device__ int   g_is64;

// ---------------- helpers -----------------------------------------------------
__device__ __forceinline__ uint32_t packbf(float a, float b) {
    __nv_bfloat162 t = __floats2bfloat162_rn(a, b);   // .x = a (low half)
    return *(uint32_t*)&t;
}
__device__ __forceinline__ float bfhi(float w) {
    return __bfloat162float(__float2bfloat16_rn(w));
}

// ---------------- edge dtype detection ---------------------------------------
__global__ void detect_kernel(const void* __restrict__ ei) {
    const long long* p64 = (const long long*)ei;
    int ok = 1;
    for (int i = 0; i < 64; i++) {
        long long v = p64[i];
        if (v < 0 || v >= N_NODES) { ok = 0; break; }
    }
    g_is64 = ok;
}

__device__ __forceinline__ int load_edge(const void* ei, long idx) {
    long long v = g_is64 ? ((const long long*)ei)[idx]
                         : (long long)((const int*)ei)[idx];
    if ((unsigned long long)v >= (unsigned long long)N_NODES) v = 0;
    return (int)v;
}

// ---------------- CSR build --------------------------------------------------
__global__ void zero_deg_kernel() {
    int i = blockIdx.x * blockDim.x + threadIdx.x;
    if (i < N_NODES) g_deg[i] = 0;
}

__global__ void count_deg_kernel(const void* __restrict__ ei) {
    int e = blockIdx.x * blockDim.x + threadIdx.x;
    if (e < N_EDGES) atomicAdd(&g_deg[load_edge(ei, (long)N_EDGES + e)], 1);
}

#define SCAN_T 1024
#define SCAN_BLOCKS ((N_NODES + SCAN_T - 1) / SCAN_T)

__global__ __launch_bounds__(SCAN_T) void scanA_kernel() {
    __shared__ int sh[SCAN_T];
    int i = blockIdx.x * SCAN_T + threadIdx.x;
    int v = (i < N_NODES) ? g_deg[i] : 0;
    sh[threadIdx.x] = v;
    __syncthreads();
    int acc = v;
    for (int off = 1; off < SCAN_T; off <<= 1) {
        int t = (threadIdx.x >= off) ? sh[threadIdx.x - off] : 0;
        __syncthreads();
        acc += t;
        sh[threadIdx.x] = acc;
        __syncthreads();
    }
    if (i < N_NODES) g_row_ptr[i] = acc - v;
    if (threadIdx.x == SCAN_T - 1) g_blocksum[blockIdx.x] = acc;
}

__global__ void scanB_kernel() {
    __shared__ int sh[128];
    int t = threadIdx.x;
    int v = (t < SCAN_BLOCKS) ? g_blocksum[t] : 0;
    sh[t] = v;
    __syncthreads();
    int acc = v;
    for (int off = 1; off < 128; off <<= 1) {
        int tv = (t >= off) ? sh[t - off] : 0;
        __syncthreads();
        acc += tv;
        sh[t] = acc;
        __syncthreads();
    }
    if (t < SCAN_BLOCKS) g_blocksum[t] = acc - v;
}

__global__ __launch_bounds__(SCAN_T) void scanC_kernel() {
    int i = blockIdx.x * SCAN_T + threadIdx.x;
    if (i < N_NODES) {
        int r = g_row_ptr[i] + g_blocksum[blockIdx.x];
        g_row_ptr[i] = r;
        g_cursor[i] = r;
        g_deg_inv[i] = 1.0f / (float)max(g_deg[i], 1);
    }
    if (i == 0) g_row_ptr[N_NODES] = N_EDGES;
}

__global__ void fill_csr_kernel(const void* __restrict__ ei) {
    int e = blockIdx.x * blockDim.x + threadIdx.x;
    if (e < N_EDGES) {
        int src = load_edge(ei, e);
        int dst = load_edge(ei, (long)N_EDGES + e);
        int p = atomicAdd(&g_cursor[dst], 1);
        if (p < N_EDGES) g_col_idx[p] = src;
    }
}

// ---------------- W pre-split to bf16 fragment-major (once per launch) --------
__global__ void wsplit_kernel(const float* __restrict__ Wl,
                              const float* __restrict__ Wr) {
    int t = blockIdx.x * 256 + threadIdx.x;           // 6*2*4*1024
    if (t >= N_CONVS * 2 * 4 * 1024) return;
    int f     = t & 1023;
    int kc    = (t >> 10) & 3;
    int mat   = (t >> 12) & 1;
    int layer = t >> 13;
    int s  = f >> 9;
    int n  = (f >> 2) & 127;
    int qq = f & 3;
    const float* W = (mat ? Wr : Wl) + (long)layer * D * D;
    int kb = kc * 32 + s * 16 + 2 * qq;
    float w0 = W[(kb + 0) * D + n];
    float w1 = W[(kb + 1) * D + n];
    float w2 = W[(kb + 8) * D + n];
    float w3 = W[(kb + 9) * D + n];
    float h0 = bfhi(w0), h1 = bfhi(w1), h2 = bfhi(w2), h3 = bfhi(w3);
    uint2 hi, lo;
    hi.x = packbf(h0, h1);        hi.y = packbf(h2, h3);
    lo.x = packbf(w0 - h0, w1 - h1);
    lo.y = packbf(w2 - h2, w3 - h3);
    uint2* dst = g_Wbf + (long)(((layer * 2 + mat) * 4 + kc)) * 2048;
    dst[f] = hi;
    dst[1024 + f] = lo;
}

// ---------------- mean aggregation: one warp per node, 4-deep ILP ------------
__global__ __launch_bounds__(256) void agg_kernel(const float* __restrict__ x,
                                                  int nodeBase, int nodeCnt) {
    int warp = (blockIdx.x * blockDim.x + threadIdx.x) >> 5;
    int lane = threadIdx.x & 31;
    if (warp >= nodeCnt) return;
    int node = nodeBase + warp;

    int e0 = g_row_ptr[node];
    int e1 = g_row_ptr[node + 1];
    const float4* x4 = (const float4*)x;

    float4 a0 = make_float4(0.f, 0.f, 0.f, 0.f);
    float4 a1 = a0, a2 = a0, a3 = a0;
    int e = e0;
    for (; e + 4 <= e1; e += 4) {
        int s0 = g_col_idx[e + 0];
        int s1 = g_col_idx[e + 1];
        int s2 = g_col_idx[e + 2];
        int s3 = g_col_idx[e + 3];
        float4 v0 = __ldg(&x4[(long)s0 * 32 + lane]);
        float4 v1 = __ldg(&x4[(long)s1 * 32 + lane]);
        float4 v2 = __ldg(&x4[(long)s2 * 32 + lane]);
        float4 v3 = __ldg(&x4[(long)s3 * 32 + lane]);
        a0.x += v0.x; a0.y += v0.y; a0.z += v0.z; a0.w += v0.w;
        a1.x += v1.x; a1.y += v1.y; a1.z += v1.z; a1.w += v1.w;
        a2.x += v2.x; a2.y += v2.y; a2.z += v2.z; a2.w += v2.w;
        a3.x += v3.x; a3.y += v3.y; a3.z += v3.z; a3.w += v3.w;
    }
    for (; e < e1; e++) {
        int s = g_col_idx[e];
        float4 v = __ldg(&x4[(long)s * 32 + lane]);
        a0.x += v.x; a0.y += v.y; a0.z += v.z; a0.w += v.w;
    }
    float di = g_deg_inv[node];
    float4 acc;
    acc.x = (a0.x + a1.x + a2.x + a3.x) * di;
    acc.y = (a0.y + a1.y + a2.y + a3.y) * di;
    acc.z = (a0.z + a1.z + a2.z + a3.z) * di;
    acc.w = (a0.w + a1.w + a2.w + a3.w) * di;
    ((float4*)g_mean)[(long)node * 32 + lane] = acc;
}

// ---------------- 3xBF16 tensor-core dual GEMM + bias + relu ------------------
// R14 kernel (double-buffered, one sync per iter) + rowBlockBase for chunking.
#define APITCH 20
#define AS_BUF_STRIDE (2 * 128 * APITCH)      // 5120 u32 per buffer
#define WS_BASE_U32   (2 * AS_BUF_STRIDE)     // 10240
#define WS_BUF_STRIDE 2048                    // uint2 per buffer (hi 1024 | lo 1024)
#define SMEM_BYTES ((WS_BASE_U32 + 2 * WS_BUF_STRIDE * 2) * 4)   // 73728 B

__device__ __forceinline__ void mma_bf16(float c[4],
                                         uint32_t a0, uint32_t a1,
                                         uint32_t a2, uint32_t a3,
                                         uint32_t b0, uint32_t b1) {
    asm volatile(
        "mma.sync.aligned.m16n8k16.row.col.f32.bf16.bf16.f32 "
        "{%0,%1,%2,%3}, {%4,%5,%6,%7}, {%8,%9}, {%0,%1,%2,%3};"
        : "+f"(c[0]), "+f"(c[1]), "+f"(c[2]), "+f"(c[3])
        : "r"(a0), "r"(a1), "r"(a2), "r"(a3), "r"(b0), "r"(b1));
}

__global__ __launch_bounds__(256, 2) void sage_gemm_bf16(
    const float* __restrict__ A0,    // mean [N,128]
    const float* __restrict__ A1,    // x    [N,128]
    const uint2* __restrict__ Wbf,   // this layer: 8*2048 uint2 (it = phase*4+kc)
    const float* __restrict__ bias,  // [128]
    float* __restrict__ Y,
    int rowBlockBase)
{
    extern __shared__ __align__(16) uint32_t dsm[];
    uint32_t* AsB = dsm;
    uint2*    WsB = (uint2*)(dsm + WS_BASE_U32);

    const int tid  = threadIdx.x;
    const int wid  = tid >> 5;
    const int lane = tid & 31;
    const int rr   = lane >> 2;
    const int qq   = lane & 3;
    const int wm   = (wid & 3) * 32;
    const int wn   = (wid >> 2) * 64;
    const int row0 = (blockIdx.x + rowBlockBase) * 128;

    float c[2][8][4];
#pragma unroll
    for (int mt = 0; mt < 2; mt++)
#pragma unroll
        for (int nt = 0; nt < 8; nt++)
#pragma unroll
            for (int i = 0; i < 4; i++) c[mt][nt][i] = 0.f;

    const float4* A4s0 = (const float4*)A0;
    const float4* A4s1 = (const float4*)A1;

    float4 va[4];
    uint4  vw[4];

    {
#pragma unroll
        for (int i = 0; i < 4; i++) {
            int idx = tid + i * 256;
            int r  = idx >> 3;
            int c4 = idx & 7;
            int rg = row0 + r;
            if (rg >= N_NODES) rg = N_NODES - 1;
            va[i] = A4s0[(long)rg * 32 + c4];
        }
        const uint4* src = (const uint4*)Wbf;
#pragma unroll
        for (int i = 0; i < 4; i++) vw[i] = src[tid + i * 256];
    }

    for (int it = 0; it < 8; ++it) {
        const int bi = it & 1;
        uint32_t* As = AsB + bi * AS_BUF_STRIDE;
        uint2*    Ws = WsB + bi * WS_BUF_STRIDE;

#pragma unroll
        for (int i = 0; i < 4; i++) {
            int idx = tid + i * 256;
            int r  = idx >> 3;
            int c4 = idx & 7;
            float4 v = va[i];
            float hx = bfhi(v.x), hy = bfhi(v.y), hz = bfhi(v.z), hw = bfhi(v.w);
            As[r * APITCH + c4 * 2 + 0] = packbf(hx, hy);
            As[r * APITCH + c4 * 2 + 1] = packbf(hz, hw);
            As[128 * APITCH + r * APITCH + c4 * 2 + 0] = packbf(v.x - hx, v.y - hy);
            As[128 * APITCH + r * APITCH + c4 * 2 + 1] = packbf(v.z - hz, v.w - hw);
        }
        {
            uint4* dst = (uint4*)Ws;
#pragma unroll
            for (int i = 0; i < 4; i++) dst[tid + i * 256] = vw[i];
        }
        __syncthreads();    // the ONLY sync per iteration

        if (it < 7) {
            int nit = it + 1;
            int kc = nit & 3;
            const float4* A4 = (nit >> 2) ? A4s1 : A4s0;
#pragma unroll
            for (int i = 0; i < 4; i++) {
                int idx = tid + i * 256;
                int r  = idx >> 3;
                int c4 = idx & 7;
                int rg = row0 + r;
                if (rg >= N_NODES) rg = N_NODES - 1;
                va[i] = A4[(long)rg * 32 + kc * 8 + c4];
            }
            const uint4* src = (const uint4*)(Wbf + (long)nit * 2048);
#pragma unroll
            for (int i = 0; i < 4; i++) vw[i] = src[tid + i * 256];
        }

#pragma unroll
        for (int s = 0; s < 2; s++) {
            uint32_t ah[2][4], al[2][4];
#pragma unroll
            for (int mt = 0; mt < 2; mt++) {
                int r = wm + mt * 16 + rr;
                int p = s * 8 + qq;
                ah[mt][0] = As[r * APITCH + p];
                ah[mt][1] = As[(r + 8) * APITCH + p];
                ah[mt][2] = As[r * APITCH + p + 4];
                ah[mt][3] = As[(r + 8) * APITCH + p + 4];
                al[mt][0] = As[128 * APITCH + r * APITCH + p];
                al[mt][1] = As[128 * APITCH + (r + 8) * APITCH + p];
                al[mt][2] = As[128 * APITCH + r * APITCH + p + 4];
                al[mt][3] = As[128 * APITCH + (r + 8) * APITCH + p + 4];
            }
#pragma unroll
            for (int nt = 0; nt < 8; nt++) {
                int widx = (s * 128 + wn + nt * 8 + rr) * 4 + qq;
                uint2 bh = Ws[widx];
                uint2 bl = Ws[1024 + widx];
#pragma unroll
                for (int mt = 0; mt < 2; mt++) {
                    mma_bf16(c[mt][nt], ah[mt][0], ah[mt][1], ah[mt][2], ah[mt][3], bh.x, bh.y);
                    mma_bf16(c[mt][nt], ah[mt][0], ah[mt][1], ah[mt][2], ah[mt][3], bl.x, bl.y);
                    mma_bf16(c[mt][nt], al[mt][0], al[mt][1], al[mt][2], al[mt][3], bh.x, bh.y);
                }
            }
        }
    }

    // epilogue: bias + relu
#pragma unroll
    for (int mt = 0; mt < 2; mt++) {
#pragma unroll
        for (int half = 0; half < 2; half++) {
            int r = row0 + wm + mt * 16 + rr + half * 8;
            if (r < N_NODES) {
#pragma unroll
                for (int nt = 0; nt < 8; nt++) {
                    int col = wn + nt * 8 + 2 * qq;
                    float v0 = c[mt][nt][half * 2 + 0] + bias[col];
                    float v1 = c[mt][nt][half * 2 + 1] + bias[col + 1];
                    float2 o;
                    o.x = fmaxf(v0, 0.f);
                    o.y = fmaxf(v1, 0.f);
                    *(float2*)&Y[(long)r * 128 + col] = o;
                }
            }
        }
    }
}

// ---------------- final linear ------------------------------------------------
__global__ __launch_bounds__(256) void final_kernel(
    const float* __restrict__ x, const float* __restrict__ W_lin,
    const float* __restrict__ b_lin, float* __restrict__ out)
{
    int warp = (blockIdx.x * blockDim.x + threadIdx.x) >> 5;
    int lane = threadIdx.x & 31;
    if (warp >= N_NODES) return;

    const float4* x4 = (const float4*)x;
    float4 xv = x4[(long)warp * 32 + lane];
    float w0 = W_lin[lane * 4 + 0];
    float w1 = W_lin[lane * 4 + 1];
    float w2 = W_lin[lane * 4 + 2];
    float w3 = W_lin[lane * 4 + 3];
    float s = xv.x * w0 + xv.y * w1 + xv.z * w2 + xv.w * w3;
#pragma unroll
    for (int off = 16; off > 0; off >>= 1)
        s += __shfl_xor_sync(0xFFFFFFFFu, s, off);
    if (lane == 0) out[warp] = s + b_lin[0];
}

// ---------------- launch ------------------------------------------------------
extern "C" void kernel_launch(void* const* d_in, const int* in_sizes, int n_in,
                              void* d_out, int out_size)
{
    const float* x     = (const float*)d_in[0];
    const void*  ei    = d_in[1];
    const float* Wl    = (const float*)d_in[2];
    const float* Wr    = (const float*)d_in[3];
    const float* b     = (const float*)d_in[4];
    const float* W_lin = (const float*)d_in[5];
    const float* b_lin = (const float*)d_in[6];
    float*       out   = (float*)d_out;

    float *bufA, *bufB, *meanp;
    uint2* wbf;
    cudaGetSymbolAddress((void**)&bufA, g_bufA);
    cudaGetSymbolAddress((void**)&bufB, g_bufB);
    cudaGetSymbolAddress((void**)&meanp, g_mean);
    cudaGetSymbolAddress((void**)&wbf, g_Wbf);

    cudaFuncSetAttribute(sage_gemm_bf16,
                         cudaFuncAttributeMaxDynamicSharedMemorySize, SMEM_BYTES);

    // side stream + events (created per call; only correctness + capture calls)
    cudaStream_t s2;
    cudaStreamCreateWithFlags(&s2, cudaStreamNonBlocking);
    cudaEvent_t evA0[N_CONVS], evG0[N_CONVS];
    for (int i = 0; i < N_CONVS; i++) {
        cudaEventCreateWithFlags(&evA0[i], cudaEventDisableTiming);
        cudaEventCreateWithFlags(&evG0[i], cudaEventDisableTiming);
    }

    detect_kernel<<<1, 1>>>(ei);
    zero_deg_kernel<<<(N_NODES + 255) / 256, 256>>>();
    count_deg_kernel<<<(N_EDGES + 255) / 256, 256>>>(ei);
    scanA_kernel<<<SCAN_BLOCKS, SCAN_T>>>();
    scanB_kernel<<<1, 128>>>();
    scanC_kernel<<<SCAN_BLOCKS, SCAN_T>>>();
    fill_csr_kernel<<<(N_EDGES + 255) / 256, 256>>>(ei);
    wsplit_kernel<<<(N_CONVS * 2 * 4 * 1024 + 255) / 256, 256>>>(Wl, Wr);

    const int aggBlocksC0 = (C0_NODES * 32 + 255) / 256;
    const int aggBlocksC1 = (C1_NODES * 32 + 255) / 256;

    const float* cur = x;
    for (int i = 0; i < N_CONVS; i++) {
        float* nxt = (i & 1) ? bufB : bufA;
        const uint2* wlayer = wbf + (long)i * 8 * 2048;
        const float* blayer = b + (long)i * D;

        // main: agg chunk0, then fork gemm(c0) to s2
        agg_kernel<<<aggBlocksC0, 256>>>(cur, 0, C0_NODES);
        cudaEventRecord(evA0[i], 0);
        cudaStreamWaitEvent(s2, evA0[i], 0);
        sage_gemm_bf16<<<C0_GBLOCKS, 256, SMEM_BYTES, s2>>>(
            meanp, cur, wlayer, blayer, nxt, 0);
        cudaEventRecord(evG0[i], s2);

        // main: agg chunk1 (concurrent with gemm c0), then gemm chunk1
        agg_kernel<<<aggBlocksC1, 256>>>(cur, C0_NODES, C1_NODES);
        sage_gemm_bf16<<<C1_GBLOCKS, 256, SMEM_BYTES>>>(
            meanp, cur, wlayer, blayer, nxt, C0_GBLOCKS);

        // join: everything after this on main sees gemm(c0)'s writes
        cudaStreamWaitEvent(0, evG0[i], 0);
        cur = nxt;
    }
    final_kernel<<<(N_NODES * 32 + 255) / 256, 256>>>(cur, W_lin, b_lin, out);
}